// round 1
// baseline (speedup 1.0000x reference)
#include <cuda_runtime.h>
#include <math.h>

// ---------------- problem constants ----------------
#define BATCH   4
#define LSEQ    1024
#define DM      512
#define DI      1024      // d_inner
#define DS      16        // d_state
#define DTR     32        // dt_rank
#define NROWS   (BATCH*LSEQ)   // 4096
#define LN_EPS  1e-5f

// ---------------- scratch (device globals; no allocs allowed) ----------------
__device__ float g_xz[NROWS * 2 * DI];   // in_proj output  [4096, 2048]
__device__ float g_xs[NROWS * DI];       // conv+silu       [4096, 1024]
__device__ float g_dbc[NROWS * 64];      // x_proj output   [4096, 64] (dt|B|C)
__device__ float g_delta[NROWS * DI];    // softplus(dt@Wdt+b)
__device__ float g_y[NROWS * DI];        // scan out, then gated
__device__ float g_res[NROWS * DM];      // out_proj + residual (LN input)

// ---------------- SGEMM: C[M,N] = A[M,K] @ B[K,N] (+ resid) ----------------
#define BM 128
#define BN 64
#define BK 16
#define TM 8
#define TN 4

__global__ __launch_bounds__(256) void sgemm_k(
    const float* __restrict__ A, const float* __restrict__ B,
    float* __restrict__ C, const float* __restrict__ resid,
    int K, int lda, int ldb, int ldc)
{
    __shared__ float As[BK][BM];
    __shared__ float Bs[BK][BN];
    const int tid = threadIdx.x;
    const int bm = blockIdx.y * BM;
    const int bn = blockIdx.x * BN;
    const int tx = tid & 15;          // 0..15 -> 64 cols
    const int ty = tid >> 4;          // 0..15 -> 128 rows
    const int ar = tid >> 2;          // 0..63
    const int ac = (tid & 3) << 2;    // 0,4,8,12
    const int br = tid >> 4;          // 0..15
    const int bc = (tid & 15) << 2;   // 0..60

    float acc[TM][TN];
#pragma unroll
    for (int i = 0; i < TM; i++)
#pragma unroll
        for (int j = 0; j < TN; j++) acc[i][j] = 0.f;

    for (int k0 = 0; k0 < K; k0 += BK) {
        float4 a0 = *(const float4*)(A + (size_t)(bm + ar)      * lda + k0 + ac);
        float4 a1 = *(const float4*)(A + (size_t)(bm + ar + 64) * lda + k0 + ac);
        float4 b0 = *(const float4*)(B + (size_t)(k0 + br) * ldb + bn + bc);
        As[ac + 0][ar] = a0.x; As[ac + 1][ar] = a0.y;
        As[ac + 2][ar] = a0.z; As[ac + 3][ar] = a0.w;
        As[ac + 0][ar + 64] = a1.x; As[ac + 1][ar + 64] = a1.y;
        As[ac + 2][ar + 64] = a1.z; As[ac + 3][ar + 64] = a1.w;
        *(float4*)(&Bs[br][bc]) = b0;
        __syncthreads();
#pragma unroll
        for (int kk = 0; kk < BK; kk++) {
            float4 aA = *(const float4*)(&As[kk][ty * TM]);
            float4 aB = *(const float4*)(&As[kk][ty * TM + 4]);
            float4 bv = *(const float4*)(&Bs[kk][tx * TN]);
            float av[8] = {aA.x, aA.y, aA.z, aA.w, aB.x, aB.y, aB.z, aB.w};
            float bw[4] = {bv.x, bv.y, bv.z, bv.w};
#pragma unroll
            for (int i = 0; i < TM; i++)
#pragma unroll
                for (int j = 0; j < TN; j++)
                    acc[i][j] = fmaf(av[i], bw[j], acc[i][j]);
        }
        __syncthreads();
    }
#pragma unroll
    for (int i = 0; i < TM; i++) {
        int row = bm + ty * TM + i;
        float4 o;
        o.x = acc[i][0]; o.y = acc[i][1]; o.z = acc[i][2]; o.w = acc[i][3];
        if (resid) {
            float4 rr = *(const float4*)(resid + (size_t)row * ldc + bn + tx * TN);
            o.x += rr.x; o.y += rr.y; o.z += rr.z; o.w += rr.w;
        }
        *(float4*)(C + (size_t)row * ldc + bn + tx * TN) = o;
    }
}

// ---------------- depthwise causal conv (k=4) + bias + silu ----------------
__global__ __launch_bounds__(256) void conv_silu_k(
    const float* __restrict__ cw, const float* __restrict__ cb)
{
    int idx = blockIdx.x * 256 + threadIdx.x;   // over NROWS*DI
    int d = idx & (DI - 1);
    int row = idx >> 10;      // DI = 1024
    int t = row & (LSEQ - 1);
    float acc = cb[d];
#pragma unroll
    for (int k = 0; k < 4; k++) {
        int tt = t - 3 + k;
        if (tt >= 0)
            acc = fmaf(g_xz[(size_t)(row - 3 + k) * (2 * DI) + d], cw[d * 4 + k], acc);
    }
    // silu
    g_xs[idx] = acc / (1.f + __expf(-acc));
}

// ---------------- delta = softplus(raw + bias) (in-place on g_delta) -------
__global__ __launch_bounds__(256) void softplus_k(const float* __restrict__ bdt)
{
    int idx = blockIdx.x * 256 + threadIdx.x;
    int d = idx & (DI - 1);
    float x = g_delta[idx] + bdt[d];
    g_delta[idx] = (x > 20.f) ? x : log1pf(expf(x));
}

// ---------------- selective scan ----------------
// 16 lanes per channel (one state each), 2 channels per warp.
__global__ __launch_bounds__(256) void scan_k(const float* __restrict__ A_log)
{
    int tid = blockIdx.x * 256 + threadIdx.x;
    int w = tid >> 5;
    int lane = tid & 31;
    int half = lane >> 4;
    int n = lane & 15;
    int b = w / (DI / 2);
    int dp = w % (DI / 2);
    int d = dp * 2 + half;

    float a = -expf(A_log[d * DS + n]);

    const float* dptr  = g_delta + (size_t)b * LSEQ * DI + d;
    const float* xptr  = g_xs    + (size_t)b * LSEQ * DI + d;
    const float* bcptr = g_dbc   + (size_t)b * LSEQ * 64;
    float*       yptr  = g_y     + (size_t)b * LSEQ * DI + d;

    float h = 0.f;
    for (int t = 0; t < LSEQ; t++) {
        float delta = __ldg(dptr);  dptr += DI;
        float xs    = __ldg(xptr);  xptr += DI;
        float Bn = __ldg(bcptr + 32 + n);
        float Cn = __ldg(bcptr + 48 + n);
        bcptr += 64;
        float dA = __expf(delta * a);
        h = fmaf(dA, h, (delta * xs) * Bn);
        float p = h * Cn;
        p += __shfl_xor_sync(0xffffffffu, p, 8);
        p += __shfl_xor_sync(0xffffffffu, p, 4);
        p += __shfl_xor_sync(0xffffffffu, p, 2);
        p += __shfl_xor_sync(0xffffffffu, p, 1);
        if (n == 0) *yptr = p;
        yptr += DI;
    }
}

// ---------------- gate: y = (y + xs*D) * silu(z) ----------------
__global__ __launch_bounds__(256) void gate_k(const float* __restrict__ Dsk)
{
    int idx = blockIdx.x * 256 + threadIdx.x;
    int d = idx & (DI - 1);
    int row = idx >> 10;
    float y = g_y[idx] + g_xs[idx] * Dsk[d];
    float z = g_xz[(size_t)row * (2 * DI) + DI + d];
    g_y[idx] = y * (z / (1.f + __expf(-z)));
}

// ---------------- layernorm over DM=512 ----------------
__global__ __launch_bounds__(256) void ln_k(
    const float* __restrict__ g, const float* __restrict__ bb,
    float* __restrict__ out)
{
    __shared__ float red[256];
    int row = blockIdx.x;
    const float* r = g_res + (size_t)row * DM;
    int tid = threadIdx.x;
    float v0 = r[tid], v1 = r[tid + 256];
    red[tid] = v0 + v1;
    __syncthreads();
    for (int o = 128; o > 0; o >>= 1) {
        if (tid < o) red[tid] += red[tid + o];
        __syncthreads();
    }
    float mean = red[0] * (1.f / 512.f);
    __syncthreads();
    float d0 = v0 - mean, d1 = v1 - mean;
    red[tid] = d0 * d0 + d1 * d1;
    __syncthreads();
    for (int o = 128; o > 0; o >>= 1) {
        if (tid < o) red[tid] += red[tid + o];
        __syncthreads();
    }
    float rs = rsqrtf(red[0] * (1.f / 512.f) + LN_EPS);
    out[(size_t)row * DM + tid]       = d0 * rs * g[tid]       + bb[tid];
    out[(size_t)row * DM + tid + 256] = d1 * rs * g[tid + 256] + bb[tid + 256];
}

// ---------------- host orchestration ----------------
extern "C" void kernel_launch(void* const* d_in, const int* in_sizes, int n_in,
                              void* d_out, int out_size)
{
    const float* x     = (const float*)d_in[0];   // [4,1024,512]
    const float* Wi    = (const float*)d_in[1];   // [2,512,2048]
    const float* cw    = (const float*)d_in[2];   // [2,1024,1,4]
    const float* cb    = (const float*)d_in[3];   // [2,1024]
    const float* Wx    = (const float*)d_in[4];   // [2,1024,64]
    const float* Wdt   = (const float*)d_in[5];   // [2,32,1024]
    const float* bdt   = (const float*)d_in[6];   // [2,1024]
    const float* A_log = (const float*)d_in[7];   // [2,1024,16]
    const float* Dsk   = (const float*)d_in[8];   // [2,1024]
    const float* Wo    = (const float*)d_in[9];   // [2,1024,512]
    const float* lng   = (const float*)d_in[10];  // [2,512]
    const float* lnb   = (const float*)d_in[11];  // [2,512]
    float* out = (float*)d_out;

    float *p_xz, *p_xs, *p_dbc, *p_delta, *p_y, *p_res;
    cudaGetSymbolAddress((void**)&p_xz, g_xz);
    cudaGetSymbolAddress((void**)&p_xs, g_xs);
    cudaGetSymbolAddress((void**)&p_dbc, g_dbc);
    cudaGetSymbolAddress((void**)&p_delta, g_delta);
    cudaGetSymbolAddress((void**)&p_y, g_y);
    cudaGetSymbolAddress((void**)&p_res, g_res);

    const int EW_BLOCKS = (NROWS * DI) / 256;   // 16384

    for (int l = 0; l < 2; l++) {
        const float* hin = (l == 0) ? x : out;

        // GEMM1: xz = hin @ Wi[l]   [4096,512]x[512,2048]
        sgemm_k<<<dim3(2 * DI / BN, NROWS / BM), 256>>>(
            hin, Wi + (size_t)l * DM * 2 * DI, p_xz, nullptr,
            DM, DM, 2 * DI, 2 * DI);

        // conv + silu
        conv_silu_k<<<EW_BLOCKS, 256>>>(cw + (size_t)l * DI * 4, cb + (size_t)l * DI);

        // GEMM2: dbc = xs @ Wx[l]   [4096,1024]x[1024,64]
        sgemm_k<<<dim3(64 / BN, NROWS / BM), 256>>>(
            p_xs, Wx + (size_t)l * DI * 64, p_dbc, nullptr,
            DI, DI, 64, 64);

        // GEMM3: delta_raw = dt @ Wdt[l]   [4096,32]x[32,1024] (dt = dbc[:, :32])
        sgemm_k<<<dim3(DI / BN, NROWS / BM), 256>>>(
            p_dbc, Wdt + (size_t)l * DTR * DI, p_delta, nullptr,
            DTR, 64, DI, DI);

        // softplus + bias
        softplus_k<<<EW_BLOCKS, 256>>>(bdt + (size_t)l * DI);

        // selective scan
        scan_k<<<(BATCH * (DI / 2) * 32) / 256, 256>>>(A_log + (size_t)l * DI * DS);

        // gate: y = (y + xs*D) * silu(z)
        gate_k<<<EW_BLOCKS, 256>>>(Dsk + (size_t)l * DI);

        // GEMM4: res = y @ Wo[l] + hin   [4096,1024]x[1024,512]
        sgemm_k<<<dim3(DM / BN, NROWS / BM), 256>>>(
            p_y, Wo + (size_t)l * DI * DM, p_res, hin,
            DI, DI, DM, DM);

        // layernorm -> out (becomes next layer's input / final output)
        ln_k<<<NROWS, 256>>>(lng + (size_t)l * DM, lnb + (size_t)l * DM, out);
    }
}